// round 16
// baseline (speedup 1.0000x reference)
#include <cuda_runtime.h>
#include <cuda_fp16.h>
#include <math.h>
#include <stdint.h>

#define D_MODEL 1024
#define SEQ     2048
#define BATCH   4
#define NHEAD   16
#define HDIM    64
#define MROWS   (BATCH*SEQ)
#define KTILES  16            // 1024 / 64 K-chunks (GEMM)
#define TILE_BYTES 16384      // GEMM tile: 128 rows * 128 bytes (64 fp16)
#define ATILE_BYTES 8192      // attention tile: 64 rows * 128 bytes
#define QSCALE 0.18033688f    // 0.125 * log2(e): scores come out in exp2 domain

// ---------------- scratch ----------------
__device__ float g_rope[SEQ*32*2];

__device__ __align__(16) __half g_xh[MROWS*D_MODEL];    // x, pre-swizzled GEMM tiles
__device__ __align__(16) __half g_ah[MROWS*D_MODEL];    // attention out, GEMM A-tiles
__device__ __align__(16) __half g_wh[4*D_MODEL*D_MODEL];
// attention operands, per-head 64x64 pre-swizzled tiles
__device__ __align__(16) __half g_qh[MROWS*D_MODEL];
__device__ __align__(16) __half g_kh[MROWS*D_MODEL];
__device__ __align__(16) __half g_vh[MROWS*D_MODEL];

// ---------------- PTX helpers (plain compute_103-safe) ----------------
__device__ __forceinline__ uint32_t smem_to_u32(const void* p) {
    uint32_t a;
    asm("{ .reg .u64 t; cvta.to.shared.u64 t, %1; cvt.u32.u64 %0, t; }" : "=r"(a) : "l"(p));
    return a;
}
__device__ __forceinline__ void cp_async16(uint32_t dst, const void* src) {
    asm volatile("cp.async.cg.shared.global [%0], [%1], 16;" :: "r"(dst), "l"(src) : "memory");
}
#define CP_COMMIT() asm volatile("cp.async.commit_group;" ::: "memory")
#define CP_WAIT(n)  asm volatile("cp.async.wait_group %0;" :: "n"(n) : "memory")

__device__ __forceinline__ void ldsm_x4(uint32_t* r, uint32_t addr) {
    asm volatile("ldmatrix.sync.aligned.m8n8.x4.shared.b16 {%0,%1,%2,%3}, [%4];"
        : "=r"(r[0]), "=r"(r[1]), "=r"(r[2]), "=r"(r[3]) : "r"(addr));
}
__device__ __forceinline__ void ldsm_x4_t(uint32_t* r, uint32_t addr) {
    asm volatile("ldmatrix.sync.aligned.m8n8.x4.trans.shared.b16 {%0,%1,%2,%3}, [%4];"
        : "=r"(r[0]), "=r"(r[1]), "=r"(r[2]), "=r"(r[3]) : "r"(addr));
}
__device__ __forceinline__ void mma_f16(float* d, const uint32_t* a, uint32_t b0, uint32_t b1) {
    asm volatile("mma.sync.aligned.m16n8k16.row.col.f32.f16.f16.f32 "
        "{%0,%1,%2,%3}, {%4,%5,%6,%7}, {%8,%9}, {%0,%1,%2,%3};"
        : "+f"(d[0]), "+f"(d[1]), "+f"(d[2]), "+f"(d[3])
        : "r"(a[0]), "r"(a[1]), "r"(a[2]), "r"(a[3]), "r"(b0), "r"(b1));
}
__device__ __forceinline__ uint32_t swz(uint32_t b) { return b ^ ((b >> 3) & 0x70); }

__device__ __forceinline__ uint32_t pack2(float a, float b) {
    __half2 h = __floats2half2_rn(a, b);
    return *(uint32_t*)&h;
}
__device__ __forceinline__ float ex2f(float x) {
    float y;
    asm("ex2.approx.ftz.f32 %0, %1;" : "=f"(y) : "f"(x));
    return y;
}

// ---------------------------------------------------------------------------
// RoPE table (double-precision angles)
// ---------------------------------------------------------------------------
__global__ void rope_table_kernel(const int* __restrict__ pos)
{
    int idx = blockIdx.x * blockDim.x + threadIdx.x;
    if (idx >= SEQ*32) return;
    int s = idx >> 5;
    int i = idx & 31;
    double freq = exp(-(double)i * (log(10000.0) / 32.0));
    double ang  = (double)pos[s] * freq;
    g_rope[idx*2+0] = (float)cos(ang);
    g_rope[idx*2+1] = (float)sin(ang);
}

// ---------------------------------------------------------------------------
// Fused fp32 -> fp16 pre-swizzled tile conversion: x + 4 weight matrices.
// ---------------------------------------------------------------------------
__global__ __launch_bounds__(256) void convert_all_kernel(
    const float* __restrict__ x,
    const float* __restrict__ wq, const float* __restrict__ wk,
    const float* __restrict__ wv, const float* __restrict__ wo,
    __half* __restrict__ xh, __half* __restrict__ wh)
{
    const int NG_X = MROWS * 128;      // 2^20
    int idx = blockIdx.x * blockDim.x + threadIdx.x;

    const float* src;
    __half* dst;
    int rel;
    if (idx < NG_X) {
        src = x; dst = xh; rel = idx;
    } else {
        int t = idx - NG_X;
        int w = t >> 17;
        rel   = t & (D_MODEL*128 - 1);
        src = (w == 0) ? wq : (w == 1) ? wk : (w == 2) ? wv : wo;
        dst = wh + (size_t)w * D_MODEL * D_MODEL;
    }
    int r = rel >> 7;
    int d = (rel & 127) << 3;

    const float4* s4 = (const float4*)(src + (size_t)r * D_MODEL + d);
    float4 f0 = s4[0], f1 = s4[1];

    union { __half h[8]; uint4 u; } H;
    H.h[0] = __float2half_rn(f0.x); H.h[1] = __float2half_rn(f0.y);
    H.h[2] = __float2half_rn(f0.z); H.h[3] = __float2half_rn(f0.w);
    H.h[4] = __float2half_rn(f1.x); H.h[5] = __float2half_rn(f1.y);
    H.h[6] = __float2half_rn(f1.z); H.h[7] = __float2half_rn(f1.w);

    int kc = d >> 6;
    uint32_t sw = swz((uint32_t)(r & 127) * 128u + (uint32_t)(d & 63) * 2u);
    size_t tb = ((size_t)(r >> 7) * KTILES + kc) * TILE_BYTES + sw;
    *(uint4*)((char*)dst + tb) = H.u;
}

// ---------------------------------------------------------------------------
// mma.sync fp16 GEMM: Out[row,e] = sum_d A[row,d] * W[e,d]
// CTA 128x128, K-chunks of 64. 8 warps, warp tile 32x64 (round-14 shape).
// 3-stage cp.async pipeline, ONE __syncthreads per chunk.
// mode 0: fp32 Out. mode 1: QKV -> fp16 per-head attention tiles
// (+RoPE z<2; z==0 additionally scaled by QSCALE so scores are exp2-domain).
// ---------------------------------------------------------------------------
__global__ __launch_bounds__(256) void gemm_mma_kernel(
    const __half* __restrict__ A,
    const __half* __restrict__ W0, const __half* __restrict__ W1, const __half* __restrict__ W2,
    float* __restrict__ OutF,
    __half* __restrict__ qh, __half* __restrict__ kh, __half* __restrict__ vh,
    int mode)
{
    extern __shared__ char smem[];
    const uint32_t sb = smem_to_u32(smem);
    const int tid = threadIdx.x;
    const int z = blockIdx.z;

    const __half* W = (z == 0) ? W0 : (z == 1) ? W1 : W2;

    const int wid = tid >> 5, lane = tid & 31;
    const int wm = wid & 3, wn = wid >> 2;
    const int lr = lane & 15, lc8 = (lane >> 4) << 3;

    const size_t aBase = (size_t)blockIdx.y * KTILES * TILE_BYTES;
    const size_t bBase = (size_t)blockIdx.x * KTILES * TILE_BYTES;
    const char* aP = (const char*)A + aBase;
    const char* bP = (const char*)W + bBase;

    // stage s at sb + s*32768, {A:0, B:16384}
    auto issue_loads = [&](int stage, int kc) {
        uint32_t dst = sb + (uint32_t)stage * 32768u;
        size_t toff = (size_t)kc * TILE_BYTES;
#pragma unroll
        for (int i = 0; i < 4; i++) {
            uint32_t o = (uint32_t)tid * 16u + (uint32_t)i * 4096u;
            cp_async16(dst + o,          aP + toff + o);
            cp_async16(dst + 16384u + o, bP + toff + o);
        }
        CP_COMMIT();
    };

    float acc[2][8][4];
#pragma unroll
    for (int i = 0; i < 2; i++)
#pragma unroll
        for (int j = 0; j < 8; j++)
#pragma unroll
            for (int q = 0; q < 4; q++) acc[i][j][q] = 0.f;

    issue_loads(0, 0);
    issue_loads(1, 1);

    for (int c = 0; c < KTILES; c++) {
        if (c + 1 < KTILES) { CP_WAIT(1); } else { CP_WAIT(0); }
        __syncthreads();   // stage c visible to all; prior compute on stage (c+2)%3 done
        if (c + 2 < KTILES) issue_loads((c + 2) % 3, c + 2);

        uint32_t base = sb + (uint32_t)(c % 3) * 32768u;
#pragma unroll
        for (int k16 = 0; k16 < 4; k16++) {
            int col = (k16 << 4) + lc8;
            uint32_t af[2][4];
#pragma unroll
            for (int mf = 0; mf < 2; mf++) {
                int row = (wm << 5) + (mf << 4) + lr;
                ldsm_x4(af[mf], base + swz(row*128u + col*2u));
            }
#pragma unroll
            for (int nf2 = 0; nf2 < 4; nf2++) {
                int brow = (wn << 6) + (nf2 << 4) + lr;
                uint32_t bf[4];
                ldsm_x4(bf, base + 16384u + swz(brow*128u + col*2u));
#pragma unroll
                for (int mf = 0; mf < 2; mf++) {
                    mma_f16(acc[mf][nf2*2],   af[mf], bf[0], bf[2]);
                    mma_f16(acc[mf][nf2*2+1], af[mf], bf[1], bf[3]);
                }
            }
        }
    }

    const int row0 = (blockIdx.y << 7) + (wm << 5) + (lane >> 2);
    const int col0 = (blockIdx.x << 7) + (wn << 6) + ((lane & 3) << 1);
    const bool rp = (mode == 1) && (z < 2);
    const bool qs = (mode == 1) && (z == 0);
    __half* DST = (z == 0) ? qh : (z == 1) ? kh : vh;

#pragma unroll
    for (int mf = 0; mf < 2; mf++) {
#pragma unroll
        for (int nf = 0; nf < 8; nf++) {
            int gc = col0 + (nf << 3);
#pragma unroll
            for (int half = 0; half < 2; half++) {
                int gr = row0 + (mf << 4) + (half << 3);
                float e = acc[mf][nf][half*2 + 0];
                float o = acc[mf][nf][half*2 + 1];
                if (rp) {
                    int s = gr & (SEQ - 1);
                    int p = (gc & 63) >> 1;
                    float cs = g_rope[(s*32 + p)*2 + 0];
                    float sn = g_rope[(s*32 + p)*2 + 1];
                    float e2 = e*cs - o*sn;
                    o = e*sn + o*cs;
                    e = e2;
                }
                if (qs) { e *= QSCALE; o *= QSCALE; }
                if (mode == 0) {
                    *(float2*)(OutF + (size_t)gr * D_MODEL + gc) = make_float2(e, o);
                } else {
                    int bb = gr >> 11, ss = gr & (SEQ-1), hh = gc >> 6, dd = gc & 63;
                    size_t off = ((size_t)((bb*NHEAD + hh)*32 + (ss >> 6))) * ATILE_BYTES
                               + swz((uint32_t)(ss & 63)*128u + (uint32_t)dd*2u);
                    *(uint32_t*)((char*)DST + off) = pack2(e, o);
                }
            }
        }
    }
}

// ---------------------------------------------------------------------------
// Flash attention, mma.sync fp16, unnormalized exp2 softmax.
// CTA = 128 q-rows of one (b,h); 4 warps x 32 rows (2 m-frags/warp).
// 128 threads, 2 CTAs/SM. K/V in a 3-stage cp.async pipeline,
// ONE __syncthreads per j-tile.
// smem: Q 16K | 3 stages x (K 8K, V 8K) = 64K
// ---------------------------------------------------------------------------
__global__ __launch_bounds__(128, 2) void flash_mma_kernel(
    const __half* __restrict__ qh_, const __half* __restrict__ kh_,
    const __half* __restrict__ vh_, __half* __restrict__ ah_)
{
    extern __shared__ char smem[];
    const uint32_t sb = smem_to_u32(smem);
    const int qi = (int)gridDim.x - 1 - (int)blockIdx.x;
    const int h = blockIdx.y, b = blockIdx.z;
    const int tid = threadIdx.x, wid = tid >> 5, lane = tid & 31;
    const int lr = lane & 15, lc8 = (lane >> 4) << 3;
    const uint32_t ONES = 0x3C003C00u;   // fp16 {1.0, 1.0}

    const size_t hb = (size_t)((b*NHEAD + h) * 32) * ATILE_BYTES;
    const char* qp = (const char*)qh_ + hb;
    const char* kp = (const char*)kh_ + hb;
    const char* vp = (const char*)vh_ + hb;

    // Q: 2 consecutive 8KB tiles (rows 128qi..128qi+127) — own commit group
    {
        size_t q0 = (size_t)(2*qi) * ATILE_BYTES;
#pragma unroll
        for (int i = 0; i < 8; i++) {
            uint32_t o = (uint32_t)tid*16u + (uint32_t)i*2048u;
            cp_async16(sb + o, qp + q0 + o);
        }
        CP_COMMIT();
    }
    auto load_kv = [&](int stage, int j0) {
        uint32_t dst = sb + 16384u + (uint32_t)stage * 16384u;
        size_t off = (size_t)j0 * ATILE_BYTES;
#pragma unroll
        for (int i = 0; i < 4; i++) {
            uint32_t o = (uint32_t)tid*16u + (uint32_t)i*2048u;
            cp_async16(dst + o,         kp + off + o);
            cp_async16(dst + 8192u + o, vp + off + o);
        }
        CP_COMMIT();
    };
    const int nj = 2*qi + 2;   // always >= 2
    load_kv(0, 0);
    load_kv(1, 1);

    float lacc[2][4];
    float ao[2][8][4];
#pragma unroll
    for (int mf = 0; mf < 2; mf++) {
#pragma unroll
        for (int q = 0; q < 4; q++) lacc[mf][q] = 0.f;
#pragma unroll
        for (int i = 0; i < 8; i++)
#pragma unroll
            for (int q = 0; q < 4; q++) ao[mf][i][q] = 0.f;
    }

    // warp owns rows wid*32 .. wid*32+31 (two 16-row m-frags)
    const uint32_t qbase = sb + (uint32_t)(wid >> 1) * 8192u;
    const int ar0 = ((wid & 1) << 5) + lr;

    for (int j0 = 0; j0 < nj; j0++) {
        if (j0 + 1 < nj) { CP_WAIT(1); } else { CP_WAIT(0); }
        __syncthreads();   // kv stage j0 (and Q on first iter) visible; stage (j0+2)%3 free
        if (j0 + 2 < nj) load_kv((j0 + 2) % 3, j0 + 2);

        uint32_t kv = sb + 16384u + (uint32_t)(j0 % 3) * 16384u;

        // ---- QK^T (exp2-domain: Q pre-scaled by 0.125*log2e) ----
        float s[2][8][4];
#pragma unroll
        for (int mf = 0; mf < 2; mf++)
#pragma unroll
            for (int i = 0; i < 8; i++)
#pragma unroll
                for (int q = 0; q < 4; q++) s[mf][i][q] = 0.f;

#pragma unroll
        for (int k16 = 0; k16 < 4; k16++) {
            int col = (k16 << 4) + lc8;
            uint32_t aq[2][4];
#pragma unroll
            for (int mf = 0; mf < 2; mf++)
                ldsm_x4(aq[mf], qbase + swz((uint32_t)(ar0 + (mf << 4))*128u + (uint32_t)col*2u));
#pragma unroll
            for (int nf2 = 0; nf2 < 4; nf2++) {
                int brow = (nf2 << 4) + lr;
                uint32_t bk[4];
                ldsm_x4(bk, kv + swz((uint32_t)brow*128u + (uint32_t)col*2u));
#pragma unroll
                for (int mf = 0; mf < 2; mf++) {
                    mma_f16(s[mf][nf2*2],   aq[mf], bk[0], bk[2]);
                    mma_f16(s[mf][nf2*2+1], aq[mf], bk[1], bk[3]);
                }
            }
        }

        if (j0 >= 2*qi) {   // diagonal tiles: causal mask
            int jc = 64*j0 + ((lane & 3) << 1);
#pragma unroll
            for (int mf = 0; mf < 2; mf++) {
                int rg0 = 128*qi + (wid << 5) + (mf << 4) + (lane >> 2);
#pragma unroll
                for (int nf = 0; nf < 8; nf++) {
                    int j = jc + nf*8;
                    if (j     > rg0)     s[mf][nf][0] = -1e30f;
                    if (j + 1 > rg0)     s[mf][nf][1] = -1e30f;
                    if (j     > rg0 + 8) s[mf][nf][2] = -1e30f;
                    if (j + 1 > rg0 + 8) s[mf][nf][3] = -1e30f;
                }
            }
        }

        // ---- P = exp2(s) (no max subtraction; statically safe) ----
#pragma unroll
        for (int mf = 0; mf < 2; mf++)
#pragma unroll
            for (int nf = 0; nf < 8; nf++) {
                s[mf][nf][0] = ex2f(s[mf][nf][0]);
                s[mf][nf][1] = ex2f(s[mf][nf][1]);
                s[mf][nf][2] = ex2f(s[mf][nf][2]);
                s[mf][nf][3] = ex2f(s[mf][nf][3]);
            }

        // ---- P @ V + P @ ones (row sums) ----
#pragma unroll
        for (int kk = 0; kk < 4; kk++) {
            uint32_t ph[2][4];
#pragma unroll
            for (int mf = 0; mf < 2; mf++) {
                ph[mf][0] = pack2(s[mf][2*kk][0],   s[mf][2*kk][1]);
                ph[mf][1] = pack2(s[mf][2*kk][2],   s[mf][2*kk][3]);
                ph[mf][2] = pack2(s[mf][2*kk+1][0], s[mf][2*kk+1][1]);
                ph[mf][3] = pack2(s[mf][2*kk+1][2], s[mf][2*kk+1][3]);
                mma_f16(lacc[mf], ph[mf], ONES, ONES);
            }
#pragma unroll
            for (int nf2 = 0; nf2 < 4; nf2++) {
                uint32_t off = swz((uint32_t)((kk << 4) + lr)*128u
                                 + (uint32_t)((nf2 << 4) + lc8)*2u);
                uint32_t vv[4];
                ldsm_x4_t(vv, kv + 8192u + off);
#pragma unroll
                for (int mf = 0; mf < 2; mf++) {
                    mma_f16(ao[mf][nf2*2],   ph[mf], vv[0], vv[1]);
                    mma_f16(ao[mf][nf2*2+1], ph[mf], vv[2], vv[3]);
                }
            }
        }
    }

    // ---- epilogue: O/l -> fp16 pre-swizzled GEMM A-tile ----
    size_t tilebase = ((size_t)((b*16 + qi)*KTILES + h)) * TILE_BYTES;
#pragma unroll
    for (int mf = 0; mf < 2; mf++) {
        float inv0 = 1.0f / lacc[mf][0], inv1 = 1.0f / lacc[mf][2];
        int r0 = (wid << 5) + (mf << 4) + (lane >> 2);
#pragma unroll
        for (int df = 0; df < 8; df++) {
            int d = df*8 + ((lane & 3) << 1);
            uint32_t o1 = swz((uint32_t)r0*128u + (uint32_t)d*2u);
            *(uint32_t*)((char*)ah_ + tilebase + o1) = pack2(ao[mf][df][0]*inv0, ao[mf][df][1]*inv0);
            uint32_t o2 = swz((uint32_t)(r0 + 8)*128u + (uint32_t)d*2u);
            *(uint32_t*)((char*)ah_ + tilebase + o2) = pack2(ao[mf][df][2]*inv1, ao[mf][df][3]*inv1);
        }
    }
}

// ---------------------------------------------------------------------------
extern "C" void kernel_launch(void* const* d_in, const int* in_sizes, int n_in,
                              void* d_out, int out_size)
{
    const float* x  = (const float*)d_in[0];
    const float* wq = (const float*)d_in[1];
    const float* wk = (const float*)d_in[2];
    const float* wv = (const float*)d_in[3];
    const float* wo = (const float*)d_in[4];
    const int*  pos = (const int*)d_in[5];
    float* out = (float*)d_out;

    __half *xh, *ah, *wh, *qh, *kh, *vh;
    cudaGetSymbolAddress((void**)&xh, g_xh);
    cudaGetSymbolAddress((void**)&ah, g_ah);
    cudaGetSymbolAddress((void**)&wh, g_wh);
    cudaGetSymbolAddress((void**)&qh, g_qh);
    cudaGetSymbolAddress((void**)&kh, g_kh);
    cudaGetSymbolAddress((void**)&vh, g_vh);

    const int WSTRIDE = D_MODEL * D_MODEL;

    rope_table_kernel<<<(SEQ*32 + 255)/256, 256>>>(pos);

    const int totalGran = MROWS*128 + 4*D_MODEL*128;
    convert_all_kernel<<<totalGran/256, 256>>>(x, wq, wk, wv, wo, xh, wh);

    const int gsmem = 3*32768;   // 96 KB (3-stage)
    cudaFuncSetAttribute(gemm_mma_kernel,
                         cudaFuncAttributeMaxDynamicSharedMemorySize, gsmem);
    gemm_mma_kernel<<<dim3(D_MODEL/128, MROWS/128, 3), 256, gsmem>>>(
        xh, wh + 0*WSTRIDE, wh + 1*WSTRIDE, wh + 2*WSTRIDE,
        out /*unused*/, qh, kh, vh, 1);

    const int fsmem = 16384 + 3*16384;   // 64 KB (3-stage)
    cudaFuncSetAttribute(flash_mma_kernel,
                         cudaFuncAttributeMaxDynamicSharedMemorySize, fsmem);
    flash_mma_kernel<<<dim3(SEQ/128, NHEAD, BATCH), 128, fsmem>>>(qh, kh, vh, ah);

    gemm_mma_kernel<<<dim3(D_MODEL/128, MROWS/128, 1), 256, gsmem>>>(
        ah, wh + 3*WSTRIDE, wh + 3*WSTRIDE, wh + 3*WSTRIDE,
        out, qh, kh, vh, 0);
}

// round 17
// speedup vs baseline: 1.5715x; 1.5715x over previous
#include <cuda_runtime.h>
#include <cuda_fp16.h>
#include <math.h>
#include <stdint.h>

#define D_MODEL 1024
#define SEQ     2048
#define BATCH   4
#define NHEAD   16
#define HDIM    64
#define MROWS   (BATCH*SEQ)
#define KTILES  16            // 1024 / 64 K-chunks (GEMM)
#define TILE_BYTES 16384      // GEMM tile: 128 rows * 128 bytes (64 fp16)
#define ATILE_BYTES 8192      // attention tile: 64 rows * 128 bytes
#define QSCALE 0.18033688f    // 0.125 * log2(e): scores come out in exp2 domain

// ---------------- scratch ----------------
__device__ float g_rope[SEQ*32*2];

__device__ __align__(16) __half g_xh[MROWS*D_MODEL];    // x, pre-swizzled GEMM tiles
__device__ __align__(16) __half g_ah[MROWS*D_MODEL];    // attention out, GEMM A-tiles
__device__ __align__(16) __half g_wh[4*D_MODEL*D_MODEL];
// attention operands, per-head 64x64 pre-swizzled tiles
__device__ __align__(16) __half g_qh[MROWS*D_MODEL];
__device__ __align__(16) __half g_kh[MROWS*D_MODEL];
__device__ __align__(16) __half g_vh[MROWS*D_MODEL];

// ---------------- PTX helpers (plain compute_103-safe) ----------------
__device__ __forceinline__ uint32_t smem_to_u32(const void* p) {
    uint32_t a;
    asm("{ .reg .u64 t; cvta.to.shared.u64 t, %1; cvt.u32.u64 %0, t; }" : "=r"(a) : "l"(p));
    return a;
}
__device__ __forceinline__ void cp_async16(uint32_t dst, const void* src) {
    asm volatile("cp.async.cg.shared.global [%0], [%1], 16;" :: "r"(dst), "l"(src) : "memory");
}
#define CP_COMMIT() asm volatile("cp.async.commit_group;" ::: "memory")
#define CP_WAIT(n)  asm volatile("cp.async.wait_group %0;" :: "n"(n) : "memory")

__device__ __forceinline__ void ldsm_x4(uint32_t* r, uint32_t addr) {
    asm volatile("ldmatrix.sync.aligned.m8n8.x4.shared.b16 {%0,%1,%2,%3}, [%4];"
        : "=r"(r[0]), "=r"(r[1]), "=r"(r[2]), "=r"(r[3]) : "r"(addr));
}
__device__ __forceinline__ void ldsm_x4_t(uint32_t* r, uint32_t addr) {
    asm volatile("ldmatrix.sync.aligned.m8n8.x4.trans.shared.b16 {%0,%1,%2,%3}, [%4];"
        : "=r"(r[0]), "=r"(r[1]), "=r"(r[2]), "=r"(r[3]) : "r"(addr));
}
__device__ __forceinline__ void mma_f16(float* d, const uint32_t* a, uint32_t b0, uint32_t b1) {
    asm volatile("mma.sync.aligned.m16n8k16.row.col.f32.f16.f16.f32 "
        "{%0,%1,%2,%3}, {%4,%5,%6,%7}, {%8,%9}, {%0,%1,%2,%3};"
        : "+f"(d[0]), "+f"(d[1]), "+f"(d[2]), "+f"(d[3])
        : "r"(a[0]), "r"(a[1]), "r"(a[2]), "r"(a[3]), "r"(b0), "r"(b1));
}
__device__ __forceinline__ uint32_t swz(uint32_t b) { return b ^ ((b >> 3) & 0x70); }

__device__ __forceinline__ uint32_t pack2(float a, float b) {
    __half2 h = __floats2half2_rn(a, b);
    return *(uint32_t*)&h;
}
__device__ __forceinline__ float ex2f(float x) {
    float y;
    asm("ex2.approx.ftz.f32 %0, %1;" : "=f"(y) : "f"(x));
    return y;
}

// ---------------------------------------------------------------------------
// RoPE table (double-precision angles)
// ---------------------------------------------------------------------------
__global__ void rope_table_kernel(const int* __restrict__ pos)
{
    int idx = blockIdx.x * blockDim.x + threadIdx.x;
    if (idx >= SEQ*32) return;
    int s = idx >> 5;
    int i = idx & 31;
    double freq = exp(-(double)i * (log(10000.0) / 32.0));
    double ang  = (double)pos[s] * freq;
    g_rope[idx*2+0] = (float)cos(ang);
    g_rope[idx*2+1] = (float)sin(ang);
}

// ---------------------------------------------------------------------------
// Fused fp32 -> fp16 pre-swizzled tile conversion: x + 4 weight matrices.
// ---------------------------------------------------------------------------
__global__ __launch_bounds__(256) void convert_all_kernel(
    const float* __restrict__ x,
    const float* __restrict__ wq, const float* __restrict__ wk,
    const float* __restrict__ wv, const float* __restrict__ wo,
    __half* __restrict__ xh, __half* __restrict__ wh)
{
    const int NG_X = MROWS * 128;      // 2^20
    int idx = blockIdx.x * blockDim.x + threadIdx.x;

    const float* src;
    __half* dst;
    int rel;
    if (idx < NG_X) {
        src = x; dst = xh; rel = idx;
    } else {
        int t = idx - NG_X;
        int w = t >> 17;
        rel   = t & (D_MODEL*128 - 1);
        src = (w == 0) ? wq : (w == 1) ? wk : (w == 2) ? wv : wo;
        dst = wh + (size_t)w * D_MODEL * D_MODEL;
    }
    int r = rel >> 7;
    int d = (rel & 127) << 3;

    const float4* s4 = (const float4*)(src + (size_t)r * D_MODEL + d);
    float4 f0 = s4[0], f1 = s4[1];

    union { __half h[8]; uint4 u; } H;
    H.h[0] = __float2half_rn(f0.x); H.h[1] = __float2half_rn(f0.y);
    H.h[2] = __float2half_rn(f0.z); H.h[3] = __float2half_rn(f0.w);
    H.h[4] = __float2half_rn(f1.x); H.h[5] = __float2half_rn(f1.y);
    H.h[6] = __float2half_rn(f1.z); H.h[7] = __float2half_rn(f1.w);

    int kc = d >> 6;
    uint32_t sw = swz((uint32_t)(r & 127) * 128u + (uint32_t)(d & 63) * 2u);
    size_t tb = ((size_t)(r >> 7) * KTILES + kc) * TILE_BYTES + sw;
    *(uint4*)((char*)dst + tb) = H.u;
}

// ---------------------------------------------------------------------------
// mma.sync fp16 GEMM (round-14 proven shape): Out[row,e] = sum_d A[row,d]*W[e,d]
// CTA 128x128, K-chunks of 64, 2-stage cp.async (issue-then-wait ordering).
// 8 warps, warp tile 32x64.
// mode 0: fp32 Out. mode 1: QKV -> fp16 per-head attention tiles
// (+RoPE z<2; z==0 additionally scaled by QSCALE so scores are exp2-domain).
// ---------------------------------------------------------------------------
__global__ __launch_bounds__(256) void gemm_mma_kernel(
    const __half* __restrict__ A,
    const __half* __restrict__ W0, const __half* __restrict__ W1, const __half* __restrict__ W2,
    float* __restrict__ OutF,
    __half* __restrict__ qh, __half* __restrict__ kh, __half* __restrict__ vh,
    int mode)
{
    extern __shared__ char smem[];
    const uint32_t sb = smem_to_u32(smem);
    const int tid = threadIdx.x;
    const int z = blockIdx.z;

    const __half* W = (z == 0) ? W0 : (z == 1) ? W1 : W2;

    const int wid = tid >> 5, lane = tid & 31;
    const int wm = wid & 3, wn = wid >> 2;
    const int lr = lane & 15, lc8 = (lane >> 4) << 3;

    const size_t aBase = (size_t)blockIdx.y * KTILES * TILE_BYTES;
    const size_t bBase = (size_t)blockIdx.x * KTILES * TILE_BYTES;
    const char* aP = (const char*)A + aBase;
    const char* bP = (const char*)W + bBase;

    auto issue_loads = [&](int stage, int kc) {
        uint32_t dst = sb + (uint32_t)stage * 32768u;
        size_t toff = (size_t)kc * TILE_BYTES;
#pragma unroll
        for (int i = 0; i < 4; i++) {
            uint32_t o = (uint32_t)tid * 16u + (uint32_t)i * 4096u;
            cp_async16(dst + o,          aP + toff + o);
            cp_async16(dst + 16384u + o, bP + toff + o);
        }
        CP_COMMIT();
    };

    float acc[2][8][4];
#pragma unroll
    for (int i = 0; i < 2; i++)
#pragma unroll
        for (int j = 0; j < 8; j++)
#pragma unroll
            for (int q = 0; q < 4; q++) acc[i][j][q] = 0.f;

    issue_loads(0, 0);

    for (int c = 0; c < KTILES; c++) {
        int cur = c & 1;
        if (c + 1 < KTILES) {
            issue_loads(1 - cur, c + 1);
            CP_WAIT(1);
        } else {
            CP_WAIT(0);
        }
        __syncthreads();

        uint32_t base = sb + (uint32_t)cur * 32768u;
#pragma unroll
        for (int k16 = 0; k16 < 4; k16++) {
            int col = (k16 << 4) + lc8;
            uint32_t af[2][4];
#pragma unroll
            for (int mf = 0; mf < 2; mf++) {
                int row = (wm << 5) + (mf << 4) + lr;
                ldsm_x4(af[mf], base + swz(row*128u + col*2u));
            }
#pragma unroll
            for (int nf2 = 0; nf2 < 4; nf2++) {
                int brow = (wn << 6) + (nf2 << 4) + lr;
                uint32_t bf[4];
                ldsm_x4(bf, base + 16384u + swz(brow*128u + col*2u));
#pragma unroll
                for (int mf = 0; mf < 2; mf++) {
                    mma_f16(acc[mf][nf2*2],   af[mf], bf[0], bf[2]);
                    mma_f16(acc[mf][nf2*2+1], af[mf], bf[1], bf[3]);
                }
            }
        }
        __syncthreads();
    }

    const int row0 = (blockIdx.y << 7) + (wm << 5) + (lane >> 2);
    const int col0 = (blockIdx.x << 7) + (wn << 6) + ((lane & 3) << 1);
    const bool rp = (mode == 1) && (z < 2);
    const bool qs = (mode == 1) && (z == 0);
    __half* DST = (z == 0) ? qh : (z == 1) ? kh : vh;

#pragma unroll
    for (int mf = 0; mf < 2; mf++) {
#pragma unroll
        for (int nf = 0; nf < 8; nf++) {
            int gc = col0 + (nf << 3);
#pragma unroll
            for (int half = 0; half < 2; half++) {
                int gr = row0 + (mf << 4) + (half << 3);
                float e = acc[mf][nf][half*2 + 0];
                float o = acc[mf][nf][half*2 + 1];
                if (rp) {
                    int s = gr & (SEQ - 1);
                    int p = (gc & 63) >> 1;
                    float cs = g_rope[(s*32 + p)*2 + 0];
                    float sn = g_rope[(s*32 + p)*2 + 1];
                    float e2 = e*cs - o*sn;
                    o = e*sn + o*cs;
                    e = e2;
                }
                if (qs) { e *= QSCALE; o *= QSCALE; }
                if (mode == 0) {
                    *(float2*)(OutF + (size_t)gr * D_MODEL + gc) = make_float2(e, o);
                } else {
                    int bb = gr >> 11, ss = gr & (SEQ-1), hh = gc >> 6, dd = gc & 63;
                    size_t off = ((size_t)((bb*NHEAD + hh)*32 + (ss >> 6))) * ATILE_BYTES
                               + swz((uint32_t)(ss & 63)*128u + (uint32_t)dd*2u);
                    *(uint32_t*)((char*)DST + off) = pack2(e, o);
                }
            }
        }
    }
}

// ---------------------------------------------------------------------------
// Flash attention (round-14 structure + Q-fragments hoisted to registers).
// mma.sync fp16, unnormalized exp2 softmax.
// CTA = 128 q-rows of one (b,h); 4 warps x 32 rows (2 m-frags/warp).
// 128 threads, 2 CTAs/SM. K/V double-buffered (issue-then-wait ordering).
// Q fragments loaded ONCE before the loop (invariant across j).
// smem: Q 16K | 2 stages x (K 8K, V 8K) = 48K
// ---------------------------------------------------------------------------
__global__ __launch_bounds__(128, 2) void flash_mma_kernel(
    const __half* __restrict__ qh_, const __half* __restrict__ kh_,
    const __half* __restrict__ vh_, __half* __restrict__ ah_)
{
    extern __shared__ char smem[];
    const uint32_t sb = smem_to_u32(smem);
    const int qi = (int)gridDim.x - 1 - (int)blockIdx.x;
    const int h = blockIdx.y, b = blockIdx.z;
    const int tid = threadIdx.x, wid = tid >> 5, lane = tid & 31;
    const int lr = lane & 15, lc8 = (lane >> 4) << 3;
    const uint32_t ONES = 0x3C003C00u;   // fp16 {1.0, 1.0}

    const size_t hb = (size_t)((b*NHEAD + h) * 32) * ATILE_BYTES;
    const char* qp = (const char*)qh_ + hb;
    const char* kp = (const char*)kh_ + hb;
    const char* vp = (const char*)vh_ + hb;

    // Q: 2 consecutive 8KB tiles (rows 128qi..128qi+127) — group G0
    {
        size_t q0 = (size_t)(2*qi) * ATILE_BYTES;
#pragma unroll
        for (int i = 0; i < 8; i++) {
            uint32_t o = (uint32_t)tid*16u + (uint32_t)i*2048u;
            cp_async16(sb + o, qp + q0 + o);
        }
        CP_COMMIT();
    }
    auto load_kv = [&](int stage, int j0) {
        uint32_t dst = sb + 16384u + (uint32_t)stage * 16384u;
        size_t off = (size_t)j0 * ATILE_BYTES;
#pragma unroll
        for (int i = 0; i < 4; i++) {
            uint32_t o = (uint32_t)tid*16u + (uint32_t)i*2048u;
            cp_async16(dst + o,         kp + off + o);
            cp_async16(dst + 8192u + o, vp + off + o);
        }
        CP_COMMIT();
    };
    load_kv(0, 0);     // group G1

    // warp owns rows wid*32 .. wid*32+31 (two 16-row m-frags)
    const uint32_t qbase = sb + (uint32_t)(wid >> 1) * 8192u;
    const int ar0 = ((wid & 1) << 5) + lr;

    // ---- Q fragments: load ONCE (invariant over the whole j loop) ----
    CP_WAIT(1);        // G0 (Q) complete; G1 (kv0) may still be in flight
    __syncthreads();   // Q smem written by all threads is visible
    uint32_t aq[2][4][4];   // [mf][k16][frag]
#pragma unroll
    for (int k16 = 0; k16 < 4; k16++) {
        int col = (k16 << 4) + lc8;
#pragma unroll
        for (int mf = 0; mf < 2; mf++)
            ldsm_x4(aq[mf][k16], qbase + swz((uint32_t)(ar0 + (mf << 4))*128u + (uint32_t)col*2u));
    }

    float lacc[2][4];
    float ao[2][8][4];
#pragma unroll
    for (int mf = 0; mf < 2; mf++) {
#pragma unroll
        for (int q = 0; q < 4; q++) lacc[mf][q] = 0.f;
#pragma unroll
        for (int i = 0; i < 8; i++)
#pragma unroll
            for (int q = 0; q < 4; q++) ao[mf][i][q] = 0.f;
    }

    const int nj = 2*qi + 2;
    for (int j0 = 0; j0 < nj; j0++) {
        int cur = j0 & 1;
        if (j0 + 1 < nj) {
            load_kv(1 - cur, j0 + 1);
            CP_WAIT(1);
        } else {
            CP_WAIT(0);
        }
        __syncthreads();
        uint32_t kv = sb + 16384u + (uint32_t)cur * 16384u;

        // ---- QK^T (exp2-domain: Q pre-scaled by 0.125*log2e) ----
        float s[2][8][4];
#pragma unroll
        for (int mf = 0; mf < 2; mf++)
#pragma unroll
            for (int i = 0; i < 8; i++)
#pragma unroll
                for (int q = 0; q < 4; q++) s[mf][i][q] = 0.f;

#pragma unroll
        for (int k16 = 0; k16 < 4; k16++) {
            int col = (k16 << 4) + lc8;
#pragma unroll
            for (int nf2 = 0; nf2 < 4; nf2++) {
                int brow = (nf2 << 4) + lr;
                uint32_t bk[4];
                ldsm_x4(bk, kv + swz((uint32_t)brow*128u + (uint32_t)col*2u));
#pragma unroll
                for (int mf = 0; mf < 2; mf++) {
                    mma_f16(s[mf][nf2*2],   aq[mf][k16], bk[0], bk[2]);
                    mma_f16(s[mf][nf2*2+1], aq[mf][k16], bk[1], bk[3]);
                }
            }
        }

        if (j0 >= 2*qi) {   // diagonal tiles: causal mask
            int jc = 64*j0 + ((lane & 3) << 1);
#pragma unroll
            for (int mf = 0; mf < 2; mf++) {
                int rg0 = 128*qi + (wid << 5) + (mf << 4) + (lane >> 2);
#pragma unroll
                for (int nf = 0; nf < 8; nf++) {
                    int j = jc + nf*8;
                    if (j     > rg0)     s[mf][nf][0] = -1e30f;
                    if (j + 1 > rg0)     s[mf][nf][1] = -1e30f;
                    if (j     > rg0 + 8) s[mf][nf][2] = -1e30f;
                    if (j + 1 > rg0 + 8) s[mf][nf][3] = -1e30f;
                }
            }
        }

        // ---- P = exp2(s) (no max subtraction; statically safe) ----
#pragma unroll
        for (int mf = 0; mf < 2; mf++)
#pragma unroll
            for (int nf = 0; nf < 8; nf++) {
                s[mf][nf][0] = ex2f(s[mf][nf][0]);
                s[mf][nf][1] = ex2f(s[mf][nf][1]);
                s[mf][nf][2] = ex2f(s[mf][nf][2]);
                s[mf][nf][3] = ex2f(s[mf][nf][3]);
            }

        // ---- P @ V + P @ ones (row sums) ----
#pragma unroll
        for (int kk = 0; kk < 4; kk++) {
            uint32_t ph[2][4];
#pragma unroll
            for (int mf = 0; mf < 2; mf++) {
                ph[mf][0] = pack2(s[mf][2*kk][0],   s[mf][2*kk][1]);
                ph[mf][1] = pack2(s[mf][2*kk][2],   s[mf][2*kk][3]);
                ph[mf][2] = pack2(s[mf][2*kk+1][0], s[mf][2*kk+1][1]);
                ph[mf][3] = pack2(s[mf][2*kk+1][2], s[mf][2*kk+1][3]);
                mma_f16(lacc[mf], ph[mf], ONES, ONES);
            }
#pragma unroll
            for (int nf2 = 0; nf2 < 4; nf2++) {
                uint32_t off = swz((uint32_t)((kk << 4) + lr)*128u
                                 + (uint32_t)((nf2 << 4) + lc8)*2u);
                uint32_t vv[4];
                ldsm_x4_t(vv, kv + 8192u + off);
#pragma unroll
                for (int mf = 0; mf < 2; mf++) {
                    mma_f16(ao[mf][nf2*2],   ph[mf], vv[0], vv[1]);
                    mma_f16(ao[mf][nf2*2+1], ph[mf], vv[2], vv[3]);
                }
            }
        }
        __syncthreads();   // all warps done with stage cur before refill
    }

    // ---- epilogue: O/l -> fp16 pre-swizzled GEMM A-tile ----
    size_t tilebase = ((size_t)((b*16 + qi)*KTILES + h)) * TILE_BYTES;
#pragma unroll
    for (int mf = 0; mf < 2; mf++) {
        float inv0 = 1.0f / lacc[mf][0], inv1 = 1.0f / lacc[mf][2];
        int r0 = (wid << 5) + (mf << 4) + (lane >> 2);
#pragma unroll
        for (int df = 0; df < 8; df++) {
            int d = df*8 + ((lane & 3) << 1);
            uint32_t o1 = swz((uint32_t)r0*128u + (uint32_t)d*2u);
            *(uint32_t*)((char*)ah_ + tilebase + o1) = pack2(ao[mf][df][0]*inv0, ao[mf][df][1]*inv0);
            uint32_t o2 = swz((uint32_t)(r0 + 8)*128u + (uint32_t)d*2u);
            *(uint32_t*)((char*)ah_ + tilebase + o2) = pack2(ao[mf][df][2]*inv1, ao[mf][df][3]*inv1);
        }
    }
}

// ---------------------------------------------------------------------------
extern "C" void kernel_launch(void* const* d_in, const int* in_sizes, int n_in,
                              void* d_out, int out_size)
{
    const float* x  = (const float*)d_in[0];
    const float* wq = (const float*)d_in[1];
    const float* wk = (const float*)d_in[2];
    const float* wv = (const float*)d_in[3];
    const float* wo = (const float*)d_in[4];
    const int*  pos = (const int*)d_in[5];
    float* out = (float*)d_out;

    __half *xh, *ah, *wh, *qh, *kh, *vh;
    cudaGetSymbolAddress((void**)&xh, g_xh);
    cudaGetSymbolAddress((void**)&ah, g_ah);
    cudaGetSymbolAddress((void**)&wh, g_wh);
    cudaGetSymbolAddress((void**)&qh, g_qh);
    cudaGetSymbolAddress((void**)&kh, g_kh);
    cudaGetSymbolAddress((void**)&vh, g_vh);

    const int WSTRIDE = D_MODEL * D_MODEL;

    rope_table_kernel<<<(SEQ*32 + 255)/256, 256>>>(pos);

    const int totalGran = MROWS*128 + 4*D_MODEL*128;
    convert_all_kernel<<<totalGran/256, 256>>>(x, wq, wk, wv, wo, xh, wh);

    const int gsmem = 2*32768;   // 64 KB (2-stage, round-14 proven)
    cudaFuncSetAttribute(gemm_mma_kernel,
                         cudaFuncAttributeMaxDynamicSharedMemorySize, gsmem);
    gemm_mma_kernel<<<dim3(D_MODEL/128, MROWS/128, 3), 256, gsmem>>>(
        xh, wh + 0*WSTRIDE, wh + 1*WSTRIDE, wh + 2*WSTRIDE,
        out /*unused*/, qh, kh, vh, 1);

    const int fsmem = 16384 + 2*16384;   // 48 KB
    cudaFuncSetAttribute(flash_mma_kernel,
                         cudaFuncAttributeMaxDynamicSharedMemorySize, fsmem);
    flash_mma_kernel<<<dim3(SEQ/128, NHEAD, BATCH), 128, fsmem>>>(qh, kh, vh, ah);

    gemm_mma_kernel<<<dim3(D_MODEL/128, MROWS/128, 1), 256, gsmem>>>(
        ah, wh + 3*WSTRIDE, wh + 3*WSTRIDE, wh + 3*WSTRIDE,
        out, qh, kh, vh, 0);
}